// round 3
// baseline (speedup 1.0000x reference)
#include <cuda_runtime.h>
#include <math.h>

// Problem shape (fixed by reference): probs [16,2,512,512] f32, gt [16,1,512,512] i32
#define BB   16
#define HH   512
#define WW   512
#define HW   (HH * WW)          // 262144 = 2^18
#define NPIX (BB * HW)          // 4194304
#define TPB  256
#define NBLK (NPIX / TPB)       // 16384

// Scratch (no cudaMalloc allowed): squared vertical distance, per-block partials.
__device__ float g_d1[NPIX];
__device__ float g_part[NBLK];

// ---------------------------------------------------------------------------
// Kernel 1: exact 1D vertical squared distance per pixel, bounded outward scan.
// Matches reference sentinels: f init -2048 -> (i+2048)^2 ; b init 2560 -> (2560-i)^2.
// Early exit is exact: first foreground hit at offset t gives t^2, and any
// larger t' yields t'^2 > t^2; loop also breaks when t^2 >= current best.
// ---------------------------------------------------------------------------
__global__ void edt_vert(const int* __restrict__ gt) {
    int idx = blockIdx.x * TPB + threadIdx.x;     // b*HW + i*W + j
    int rem = idx & (HW - 1);                     // i*W + j
    int j   = idx & (WW - 1);
    int i   = rem >> 9;                           // W = 512 = 2^9
    const int* g = gt + (idx - rem);              // image base for batch b

    float best;
    if (g[rem] != 0) {
        best = 0.0f;
    } else {
        float fi = (float)i;
        float su = fi + 2048.0f;                  // reference forward sentinel
        float sd = 2560.0f - fi;                  // reference backward sentinel
        best = fminf(su * su, sd * sd);
        #pragma unroll 4
        for (int t = 1; t < HH; ++t) {
            float t2 = (float)(t * t);
            if (t2 >= best) break;
            int iu = i - t, id = i + t;
            bool hit = false;
            if (iu >= 0) hit = (g[iu * WW + j] != 0);
            if (id < HH) hit = hit || (g[id * WW + j] != 0);
            if (hit) { best = t2; break; }
        }
    }
    g_d1[idx] = best;
}

// ---------------------------------------------------------------------------
// Kernel 2: horizontal min-plus with parabola, bounded scan + fused epilogue.
// d2[j] = min_{j'} d1[j'] + (j-j')^2 ; since d1 >= 0, any t with t^2 >= best
// cannot improve -> early exit. Then p * sqrt(d2), block-tree reduce (fp32,
// deterministic), one partial per block (no float atomics).
// ---------------------------------------------------------------------------
__global__ void edt_horiz(const float* __restrict__ probs) {
    int idx = blockIdx.x * TPB + threadIdx.x;
    int rem = idx & (HW - 1);
    int j   = idx & (WW - 1);
    int b   = idx >> 18;                          // / HW
    const float* drow = g_d1 + (idx - j);

    float best = drow[j];
    #pragma unroll 4
    for (int t = 1; t < WW; ++t) {
        float t2 = (float)(t * t);
        if (t2 >= best) break;
        int jm = j - t, jp = j + t;
        if (jm >= 0) best = fminf(best, drow[jm] + t2);
        if (jp < WW) best = fminf(best, drow[jp] + t2);
    }

    // probs channel 0 of batch b: offset b * (2*H*W) + i*W + j
    float p = probs[(size_t)b * (size_t)(2 * HW) + (size_t)rem];
    float v = p * sqrtf(best);

    __shared__ float s[TPB];
    int tx = threadIdx.x;
    s[tx] = v;
    __syncthreads();
    #pragma unroll
    for (int off = TPB / 2; off > 0; off >>= 1) {
        if (tx < off) s[tx] += s[tx + off];
        __syncthreads();
    }
    if (tx == 0) g_part[blockIdx.x] = s[0];
}

// ---------------------------------------------------------------------------
// Kernel 3: deterministic final reduction of 16384 partials in double, write mean.
// ---------------------------------------------------------------------------
__global__ void finalize(float* __restrict__ out) {
    __shared__ double s[TPB];
    int tx = threadIdx.x;
    double acc = 0.0;
    for (int k = tx; k < NBLK; k += TPB) acc += (double)g_part[k];
    s[tx] = acc;
    __syncthreads();
    #pragma unroll
    for (int off = TPB / 2; off > 0; off >>= 1) {
        if (tx < off) s[tx] += s[tx + off];
        __syncthreads();
    }
    if (tx == 0) out[0] = (float)(s[0] / (double)NPIX);
}

extern "C" void kernel_launch(void* const* d_in, const int* in_sizes, int n_in,
                              void* d_out, int out_size) {
    const float* probs = (const float*)d_in[0];   // [16,2,512,512] f32
    const int*   gt    = (const int*)d_in[1];     // [16,1,512,512] i32
    float* out = (float*)d_out;                   // scalar f32

    edt_vert<<<NBLK, TPB>>>(gt);
    edt_horiz<<<NBLK, TPB>>>(probs);
    finalize<<<1, TPB>>>(out);
}

// round 4
// speedup vs baseline: 1.6637x; 1.6637x over previous
#include <cuda_runtime.h>
#include <math.h>

// Shapes fixed by reference: probs [16,2,512,512] f32, gt [16,1,512,512] i32
#define BB    16
#define HH    512
#define WW    512
#define HW    (HH * WW)           // 262144
#define NPIX  (BB * HW)           // 4194304
#define NWORD 16                  // 512 rows / 32 bits
#define NMASK (BB * NWORD * WW)   // 131072 words = 512KB
#define NROWB (BB * HH)           // 8192 row-blocks

// Scratch (__device__ globals; no cudaMalloc allowed)
__device__ unsigned g_mask[NMASK];   // [b][w][j] : bit k = gt at row w*32+k, col j
__device__ float    g_part[NROWB];   // per-row-block partial sums

// ---------------------------------------------------------------------------
// Kernel 1: pack gt columns into bitmasks. Thread -> (b, w, j); 32 coalesced,
// independent loads per thread (full MLP), single word store.
// ---------------------------------------------------------------------------
__global__ void pack_bits(const int* __restrict__ gt) {
    int idx = blockIdx.x * 256 + threadIdx.x;   // b*8192 + w*512 + j
    int j = idx & (WW - 1);
    int w = (idx >> 9) & (NWORD - 1);
    int b = idx >> 13;
    const int* g = gt + (size_t)b * HW + (size_t)(w * 32) * WW + j;
    unsigned word = 0u;
    #pragma unroll
    for (int k = 0; k < 32; ++k)
        word |= (g[(size_t)k * WW] != 0) ? (1u << k) : 0u;
    g_mask[idx] = word;
}

// ---------------------------------------------------------------------------
// Kernel 2: one block per (b, i) image row, 512 threads (one per column j).
//  - vertical squared distance from bitmask via clz/ffs (common case: 1 load)
//    sentinels match reference exactly: no-fg-above -> (i+2048)^2,
//    no-fg-below -> (2560-i)^2.
//  - horizontal min-plus parabola scan over the row staged in SMEM, early-exit.
//  - fused p * sqrt(d2) and deterministic block tree reduction.
// ---------------------------------------------------------------------------
__global__ void edt_main(const float* __restrict__ probs) {
    __shared__ float sd1[WW];

    int bi = blockIdx.x;             // b*512 + i
    int b  = bi >> 9;
    int i  = bi & (HH - 1);
    int j  = threadIdx.x;

    const unsigned* M = g_mask + b * (NWORD * WW);
    int w = i >> 5, r = i & 31;
    unsigned word = M[w * WW + j];

    // nearest foreground at-or-above
    unsigned mup = word & (0xFFFFFFFFu >> (31 - r));   // bits <= r
    float du;
    if (mup) {
        du = (float)(r - (31 - __clz(mup)));
    } else {
        du = (float)(i + 2048);                        // reference sentinel
        for (int w2 = w - 1; w2 >= 0; --w2) {
            unsigned mm = M[w2 * WW + j];
            if (mm) { du = (float)(i - (w2 * 32 + 31 - __clz(mm))); break; }
        }
    }

    // nearest foreground at-or-below
    unsigned mdn = word & (0xFFFFFFFFu << r);          // bits >= r
    float dd;
    if (mdn) {
        dd = (float)((__ffs(mdn) - 1) - r);
    } else {
        dd = (float)(2560 - i);                        // reference sentinel
        for (int w2 = w + 1; w2 < NWORD; ++w2) {
            unsigned mm = M[w2 * WW + j];
            if (mm) { dd = (float)(w2 * 32 + (__ffs(mm) - 1) - i); break; }
        }
    }

    float d1 = fminf(du * du, dd * dd);
    sd1[j] = d1;
    __syncthreads();

    // exact horizontal min-plus with early exit (d1 >= 0 => t^2 >= best can't win)
    float best = d1;
    #pragma unroll 4
    for (int t = 1; t < WW; ++t) {
        float t2 = (float)(t * t);
        if (t2 >= best) break;
        int jm = j - t, jp = j + t;
        if (jm >= 0) best = fminf(best, sd1[jm] + t2);
        if (jp < WW) best = fminf(best, sd1[jp] + t2);
    }

    // probs[b][0][i][j]
    float p = probs[(size_t)b * (size_t)(2 * HW) + (size_t)i * WW + j];
    float v = p * sqrtf(best);

    // deterministic block reduction (reuse sd1 after a sync)
    __syncthreads();
    sd1[j] = v;
    __syncthreads();
    #pragma unroll
    for (int off = WW / 2; off > 0; off >>= 1) {
        if (j < off) sd1[j] += sd1[j + off];
        __syncthreads();
    }
    if (j == 0) g_part[bi] = sd1[0];
}

// ---------------------------------------------------------------------------
// Kernel 3: deterministic final reduction in double, write mean.
// ---------------------------------------------------------------------------
__global__ void finalize(float* __restrict__ out) {
    __shared__ double s[256];
    int tx = threadIdx.x;
    double acc = 0.0;
    for (int k = tx; k < NROWB; k += 256) acc += (double)g_part[k];
    s[tx] = acc;
    __syncthreads();
    #pragma unroll
    for (int off = 128; off > 0; off >>= 1) {
        if (tx < off) s[tx] += s[tx + off];
        __syncthreads();
    }
    if (tx == 0) out[0] = (float)(s[0] / (double)NPIX);
}

extern "C" void kernel_launch(void* const* d_in, const int* in_sizes, int n_in,
                              void* d_out, int out_size) {
    const float* probs = (const float*)d_in[0];   // [16,2,512,512] f32
    const int*   gt    = (const int*)d_in[1];     // [16,1,512,512] i32
    float* out = (float*)d_out;                   // scalar f32

    pack_bits<<<NMASK / 256, 256>>>(gt);
    edt_main<<<NROWB, WW>>>(probs);
    finalize<<<1, 256>>>(out);
}